// round 2
// baseline (speedup 1.0000x reference)
#include <cuda_runtime.h>
#include <cstdint>
#include <math.h>

#define NHEADS 12
#define NWIN   1152
#define NTOK   64
#define CDIM   384
#define DH     32
#define MROWS  (NWIN * NTOK)   // 73728

typedef unsigned long long ull;

// ---------------------------------------------------------------------------
// Device-global scratch
// ---------------------------------------------------------------------------
__device__ float g_Q [MROWS * CDIM];
__device__ float g_K [MROWS * CDIM];
__device__ float g_V [MROWS * CDIM];
__device__ float g_AO[MROWS * CDIM];
__device__ float g_tb[225 * NHEADS];
__device__ float g_ls[NHEADS];

// ---------------------------------------------------------------------------
// f32x2 packed helpers
// ---------------------------------------------------------------------------
__device__ __forceinline__ ull fma2(ull a, ull b, ull c)
{
    ull d;
    asm("fma.rn.f32x2 %0, %1, %2, %3;" : "=l"(d) : "l"(a), "l"(b), "l"(c));
    return d;
}
__device__ __forceinline__ ull add2(ull a, ull b)
{
    ull d;
    asm("add.rn.f32x2 %0, %1, %2;" : "=l"(d) : "l"(a), "l"(b));
    return d;
}
__device__ __forceinline__ ull pk2(float lo, float hi)
{
    ull r;
    asm("mov.b64 %0, {%1, %2};" : "=l"(r) : "f"(lo), "f"(hi));
    return r;
}
__device__ __forceinline__ float2 upk2(ull v)
{
    float lo, hi;
    asm("mov.b64 {%0, %1}, %2;" : "=f"(lo), "=f"(hi) : "l"(v));
    return make_float2(lo, hi);
}

// ---------------------------------------------------------------------------
// Kernel 1: continuous position bias MLP
// ---------------------------------------------------------------------------
__global__ void cpb_kernel(const float* __restrict__ w1, const float* __restrict__ b1,
                           const float* __restrict__ w2, const float* __restrict__ b2,
                           const float* __restrict__ tau)
{
    __shared__ float red[128][12];
    const int m   = blockIdx.x;
    const int tid = threadIdx.x;
    const int ai  = m / 15;
    const int bi  = m % 15;

    float x0 = (float)(bi - 7) * (8.0f / 7.0f);
    float x1 = (float)(ai - 7) * (8.0f / 7.0f);
    float s0 = (x0 > 0.f) ? 1.f : ((x0 < 0.f) ? -1.f : 0.f);
    float s1 = (x1 > 0.f) ? 1.f : ((x1 < 0.f) ? -1.f : 0.f);
    float v0 = s0 * log2f(fabsf(x0) + 1.0f) * (1.0f / 3.0f);
    float v1 = s1 * log2f(fabsf(x1) + 1.0f) * (1.0f / 3.0f);

    float p[NHEADS];
    #pragma unroll
    for (int h = 0; h < NHEADS; h++) p[h] = 0.f;

    for (int c = tid; c < 512; c += 128) {
        float hv = v0 * w1[c] + v1 * w1[512 + c] + b1[c];
        hv = fmaxf(hv, 0.0f);
        #pragma unroll
        for (int h = 0; h < NHEADS; h++) p[h] += hv * w2[c * NHEADS + h];
    }
    #pragma unroll
    for (int h = 0; h < NHEADS; h++) red[tid][h] = p[h];
    __syncthreads();

    if (tid < NHEADS) {
        float s = 0.f;
        for (int t2 = 0; t2 < 128; t2++) s += red[t2][tid];
        g_tb[m * NHEADS + tid] = s + b2[tid];
        if (m == 0) {
            g_ls[tid] = fmaxf(tau[tid] + 2.302585092994046f, 0.01f);
        }
    }
}

// ---------------------------------------------------------------------------
// tf32 split + mma
// ---------------------------------------------------------------------------
__device__ __forceinline__ void split_store(float x, float* hi_p, float* lo_p)
{
    uint32_t h;
    asm("cvt.rna.tf32.f32 %0, %1;" : "=r"(h) : "f"(x));
    float hf = __uint_as_float(h);
    float lf = x - hf;
    uint32_t l;
    asm("cvt.rna.tf32.f32 %0, %1;" : "=r"(l) : "f"(lf));
    *hi_p = hf;
    *lo_p = __uint_as_float(l);
}

__device__ __forceinline__ void mma_tf32(float c[4], const uint32_t a[4], const uint32_t b[2])
{
    asm volatile(
        "mma.sync.aligned.m16n8k8.row.col.f32.tf32.tf32.f32 "
        "{%0,%1,%2,%3},{%4,%5,%6,%7},{%8,%9},{%0,%1,%2,%3};"
        : "+f"(c[0]), "+f"(c[1]), "+f"(c[2]), "+f"(c[3])
        : "r"(a[0]), "r"(a[1]), "r"(a[2]), "r"(a[3]), "r"(b[0]), "r"(b[1]));
}

// ---------------------------------------------------------------------------
// Kernel 2: C[M,384] = A[M,384] @ W[384,384] (+ bias), 3xTF32.
// Split done ONCE at SMEM staging; inner loop is LDS + MMA only.
// Register prefetch of next tile overlaps gmem with compute.
// Block tile 128x64, BK=16, 8 warps (4x2), warp tile 32x32. block=256.
// ---------------------------------------------------------------------------
__global__ __launch_bounds__(256) void gemm384_kernel(
    const float* __restrict__ A, const float* __restrict__ W,
    const float* __restrict__ bias, float* __restrict__ C)
{
    __shared__ float As_hi[128][20];
    __shared__ float As_lo[128][20];
    __shared__ float Ws_hi[16][72];
    __shared__ float Ws_lo[16][72];

    const int tid  = threadIdx.x;
    const int lane = tid & 31;
    const int warp = tid >> 5;
    const int wm   = warp >> 1;
    const int wn   = warp & 1;
    const int rb   = blockIdx.x * 128;
    const int cb   = blockIdx.y * 64;
    const int g    = lane >> 2;
    const int t    = lane & 3;

    // staging addresses
    const int ar = tid >> 2;         // 0..63 (i=0), +64 for i=1
    const int ac = (tid & 3) << 2;   // 0,4,8,12
    const int wr = tid >> 4;         // 0..15
    const int wc = (tid & 15) << 2;  // 0..60

    float acc[2][4][4];
    #pragma unroll
    for (int mi = 0; mi < 2; mi++)
        #pragma unroll
        for (int ni = 0; ni < 4; ni++)
            #pragma unroll
            for (int q = 0; q < 4; q++) acc[mi][ni][q] = 0.f;

    const float* aPtr0 = &A[(size_t)(rb + ar) * 384 + ac];
    const float* aPtr1 = &A[(size_t)(rb + ar + 64) * 384 + ac];
    const float* wPtr  = &W[(size_t)wr * 384 + cb + wc];

    float4 aReg0 = *reinterpret_cast<const float4*>(aPtr0);
    float4 aReg1 = *reinterpret_cast<const float4*>(aPtr1);
    float4 wReg  = *reinterpret_cast<const float4*>(wPtr);

    for (int k0 = 0; k0 < 384; k0 += 16) {
        // split-store staged tile
        split_store(aReg0.x, &As_hi[ar][ac + 0], &As_lo[ar][ac + 0]);
        split_store(aReg0.y, &As_hi[ar][ac + 1], &As_lo[ar][ac + 1]);
        split_store(aReg0.z, &As_hi[ar][ac + 2], &As_lo[ar][ac + 2]);
        split_store(aReg0.w, &As_hi[ar][ac + 3], &As_lo[ar][ac + 3]);
        split_store(aReg1.x, &As_hi[ar + 64][ac + 0], &As_lo[ar + 64][ac + 0]);
        split_store(aReg1.y, &As_hi[ar + 64][ac + 1], &As_lo[ar + 64][ac + 1]);
        split_store(aReg1.z, &As_hi[ar + 64][ac + 2], &As_lo[ar + 64][ac + 2]);
        split_store(aReg1.w, &As_hi[ar + 64][ac + 3], &As_lo[ar + 64][ac + 3]);
        split_store(wReg.x, &Ws_hi[wr][wc + 0], &Ws_lo[wr][wc + 0]);
        split_store(wReg.y, &Ws_hi[wr][wc + 1], &Ws_lo[wr][wc + 1]);
        split_store(wReg.z, &Ws_hi[wr][wc + 2], &Ws_lo[wr][wc + 2]);
        split_store(wReg.w, &Ws_hi[wr][wc + 3], &Ws_lo[wr][wc + 3]);
        __syncthreads();

        // prefetch next tile
        if (k0 + 16 < 384) {
            aReg0 = *reinterpret_cast<const float4*>(aPtr0 + k0 + 16);
            aReg1 = *reinterpret_cast<const float4*>(aPtr1 + k0 + 16);
            wReg  = *reinterpret_cast<const float4*>(wPtr + (size_t)(k0 + 16) * 384);
        }

        #pragma unroll
        for (int ks = 0; ks < 2; ks++) {
            uint32_t ahi[2][4], alo[2][4];
            #pragma unroll
            for (int mi = 0; mi < 2; mi++) {
                int r0 = wm * 32 + mi * 16 + g;
                int c0 = ks * 8 + t;
                ahi[mi][0] = __float_as_uint(As_hi[r0    ][c0    ]);
                ahi[mi][1] = __float_as_uint(As_hi[r0 + 8][c0    ]);
                ahi[mi][2] = __float_as_uint(As_hi[r0    ][c0 + 4]);
                ahi[mi][3] = __float_as_uint(As_hi[r0 + 8][c0 + 4]);
                alo[mi][0] = __float_as_uint(As_lo[r0    ][c0    ]);
                alo[mi][1] = __float_as_uint(As_lo[r0 + 8][c0    ]);
                alo[mi][2] = __float_as_uint(As_lo[r0    ][c0 + 4]);
                alo[mi][3] = __float_as_uint(As_lo[r0 + 8][c0 + 4]);
            }
            uint32_t bhi[4][2], blo[4][2];
            #pragma unroll
            for (int ni = 0; ni < 4; ni++) {
                int kk = ks * 8 + t;
                int nn = wn * 32 + ni * 8 + g;
                bhi[ni][0] = __float_as_uint(Ws_hi[kk    ][nn]);
                bhi[ni][1] = __float_as_uint(Ws_hi[kk + 4][nn]);
                blo[ni][0] = __float_as_uint(Ws_lo[kk    ][nn]);
                blo[ni][1] = __float_as_uint(Ws_lo[kk + 4][nn]);
            }
            #pragma unroll
            for (int mi = 0; mi < 2; mi++)
                #pragma unroll
                for (int ni = 0; ni < 4; ni++) {
                    mma_tf32(acc[mi][ni], ahi[mi], blo[ni]);
                    mma_tf32(acc[mi][ni], alo[mi], bhi[ni]);
                    mma_tf32(acc[mi][ni], ahi[mi], bhi[ni]);
                }
        }
        __syncthreads();
    }

    #pragma unroll
    for (int mi = 0; mi < 2; mi++) {
        #pragma unroll
        for (int ni = 0; ni < 4; ni++) {
            int r  = rb + wm * 32 + mi * 16 + g;
            int cc = cb + wn * 32 + ni * 8 + t * 2;
            float b0 = bias ? bias[cc]     : 0.f;
            float b1 = bias ? bias[cc + 1] : 0.f;
            C[(size_t)r * 384 + cc]           = acc[mi][ni][0] + b0;
            C[(size_t)r * 384 + cc + 1]       = acc[mi][ni][1] + b1;
            C[(size_t)(r + 8) * 384 + cc]     = acc[mi][ni][2] + b0;
            C[(size_t)(r + 8) * 384 + cc + 1] = acc[mi][ni][3] + b1;
        }
    }
}

// ---------------------------------------------------------------------------
// Kernel 3: per-(window, head) attention, f32x2-packed math
// grid = (1152, 12), block = 128
// ---------------------------------------------------------------------------
__global__ __launch_bounds__(128) void attn_kernel(const float* __restrict__ mask)
{
    __shared__ float qs [NTOK * DH];
    __shared__ float kss[NTOK * DH];
    __shared__ float vss[NTOK * DH];
    __shared__ float at [NTOK * 65];
    __shared__ float qn [NTOK];
    __shared__ float kn [NTOK];
    __shared__ float tbs[225];

    const int b   = blockIdx.x;
    const int h   = blockIdx.y;
    const int tid = threadIdx.x;
    const size_t base = (size_t)b * NTOK * CDIM + h * DH;

    for (int idx = tid; idx < 512; idx += 128) {
        int n = idx >> 3;
        int d = (idx & 7) << 2;
        size_t ga = base + (size_t)n * CDIM + d;
        *reinterpret_cast<float4*>(&qs [n * DH + d]) = *reinterpret_cast<const float4*>(&g_Q[ga]);
        *reinterpret_cast<float4*>(&kss[n * DH + d]) = *reinterpret_cast<const float4*>(&g_K[ga]);
        *reinterpret_cast<float4*>(&vss[n * DH + d]) = *reinterpret_cast<const float4*>(&g_V[ga]);
    }
    for (int i = tid; i < 225; i += 128) tbs[i] = g_tb[i * NHEADS + h];
    const float ls = g_ls[h];
    __syncthreads();

    // norms (f32x2)
    {
        const float* src = (tid < 64) ? qs : kss;
        int i = (tid < 64) ? tid : (tid - 64);
        const ulonglong2* p = reinterpret_cast<const ulonglong2*>(&src[i * DH]);
        ull a0 = 0ull, a1 = 0ull;
        #pragma unroll
        for (int u = 0; u < 8; u++) {
            ulonglong2 v = p[u];
            a0 = fma2(v.x, v.x, a0);
            a1 = fma2(v.y, v.y, a1);
        }
        float2 s2 = upk2(add2(a0, a1));
        float nrm = sqrtf(s2.x + s2.y);
        if (tid < 64) qn[i] = nrm; else kn[i] = nrm;
    }
    __syncthreads();

    // logits: thread (i = tid>>1, cg = tid&1) computes 32 columns
    {
        const int i  = tid >> 1;
        const int cg = tid & 1;
        ull q2[16];
        {
            const ulonglong2* qp = reinterpret_cast<const ulonglong2*>(&qs[i * DH]);
            #pragma unroll
            for (int u = 0; u < 8; u++) { ulonglong2 v = qp[u]; q2[2 * u] = v.x; q2[2 * u + 1] = v.y; }
        }
        const float qni = qn[i];
        const int ri = i >> 3, ci = i & 7;
        #pragma unroll 4
        for (int jj = 0; jj < 32; jj++) {
            int j = cg * 32 + jj;
            const ulonglong2* kp = reinterpret_cast<const ulonglong2*>(&kss[j * DH]);
            ull a0 = 0ull, a1 = 0ull, a2 = 0ull, a3 = 0ull;
            #pragma unroll
            for (int u = 0; u < 4; u++) {
                ulonglong2 v0 = kp[2 * u];
                ulonglong2 v1 = kp[2 * u + 1];
                a0 = fma2(q2[4 * u    ], v0.x, a0);
                a1 = fma2(q2[4 * u + 1], v0.y, a1);
                a2 = fma2(q2[4 * u + 2], v1.x, a2);
                a3 = fma2(q2[4 * u + 3], v1.y, a3);
            }
            float2 s2 = upk2(add2(add2(a0, a1), add2(a2, a3)));
            float dot = s2.x + s2.y;
            float den = fmaxf(qni * kn[j], 1e-6f);
            int idx = ((ri - (j >> 3)) + 7) * 15 + (ci - (j & 7)) + 7;
            float bias = 16.0f / (1.0f + __expf(-tbs[idx]));
            at[i * 65 + j] = dot / den * ls + bias;
        }
    }
    __syncthreads();

    // add mask
    {
        const float* mrow = mask + (size_t)b * 4096;
        for (int idx = tid; idx < 1024; idx += 128) {
            float4 mv = reinterpret_cast<const float4*>(mrow)[idx];
            int f = idx << 2;
            int i = f >> 6, j = f & 63;
            at[i * 65 + j]     += mv.x;
            at[i * 65 + j + 1] += mv.y;
            at[i * 65 + j + 2] += mv.z;
            at[i * 65 + j + 3] += mv.w;
        }
    }
    __syncthreads();

    // softmax per row
    if (tid < 64) {
        float* row = &at[tid * 65];
        float m = row[0];
        #pragma unroll 8
        for (int j = 1; j < 64; j++) m = fmaxf(m, row[j]);
        float s = 0.f;
        #pragma unroll 8
        for (int j = 0; j < 64; j++) { float e = __expf(row[j] - m); row[j] = e; s += e; }
        float inv = 1.0f / s;
        #pragma unroll 8
        for (int j = 0; j < 64; j++) row[j] *= inv;
    }
    __syncthreads();

    // AV (f32x2): thread (i, cg) computes 16 outputs
    {
        const int i  = tid >> 1;
        const int cg = tid & 1;
        ull acc2[8];
        #pragma unroll
        for (int u = 0; u < 8; u++) acc2[u] = 0ull;
        #pragma unroll 4
        for (int j = 0; j < 64; j++) {
            float p = at[i * 65 + j];
            ull p2 = pk2(p, p);
            const ulonglong2* vp = reinterpret_cast<const ulonglong2*>(&vss[j * DH + cg * 16]);
            #pragma unroll
            for (int u = 0; u < 4; u++) {
                ulonglong2 v = vp[u];
                acc2[2 * u]     = fma2(p2, v.x, acc2[2 * u]);
                acc2[2 * u + 1] = fma2(p2, v.y, acc2[2 * u + 1]);
            }
        }
        size_t ob = (size_t)(b * NTOK + i) * CDIM + h * DH + cg * 16;
        #pragma unroll
        for (int u = 0; u < 4; u++) {
            ulonglong2 st;
            st.x = acc2[2 * u];
            st.y = acc2[2 * u + 1];
            *reinterpret_cast<ulonglong2*>(&g_AO[ob + 4 * u]) = st;
        }
    }
}

// ---------------------------------------------------------------------------
// Launch
// ---------------------------------------------------------------------------
extern "C" void kernel_launch(void* const* d_in, const int* in_sizes, int n_in,
                              void* d_out, int out_size)
{
    (void)in_sizes; (void)n_in; (void)out_size;
    const float* x     = (const float*)d_in[0];
    const float* mask  = (const float*)d_in[1];
    const float* wq    = (const float*)d_in[2];
    const float* bq    = (const float*)d_in[3];
    const float* wk    = (const float*)d_in[4];
    const float* wv    = (const float*)d_in[5];
    const float* bv    = (const float*)d_in[6];
    const float* cw1   = (const float*)d_in[7];
    const float* cb1   = (const float*)d_in[8];
    const float* cw2   = (const float*)d_in[9];
    const float* cb2   = (const float*)d_in[10];
    const float* tau   = (const float*)d_in[11];
    const float* wproj = (const float*)d_in[12];
    const float* bproj = (const float*)d_in[13];
    float* out = (float*)d_out;

    float *pQ, *pK, *pV, *pAO;
    cudaGetSymbolAddress((void**)&pQ,  g_Q);
    cudaGetSymbolAddress((void**)&pK,  g_K);
    cudaGetSymbolAddress((void**)&pV,  g_V);
    cudaGetSymbolAddress((void**)&pAO, g_AO);

    cpb_kernel<<<225, 128>>>(cw1, cb1, cw2, cb2, tau);

    dim3 gg(MROWS / 128, CDIM / 64);
    gemm384_kernel<<<gg, 256>>>(x, wq, bq,      pQ);
    gemm384_kernel<<<gg, 256>>>(x, wk, nullptr, pK);
    gemm384_kernel<<<gg, 256>>>(x, wv, bv,      pV);

    attn_kernel<<<dim3(NWIN, NHEADS), 128>>>(mask);

    gemm384_kernel<<<gg, 256>>>(pAO, wproj, bproj, out);
}

// round 3
// speedup vs baseline: 1.6562x; 1.6562x over previous
#include <cuda_runtime.h>
#include <cuda_bf16.h>
#include <cstdint>
#include <math.h>

#define NHEADS 12
#define NWIN   1152
#define NTOK   64
#define CDIM   384
#define DH     32
#define MROWS  (NWIN * NTOK)   // 73728

typedef unsigned long long ull;

// ---------------------------------------------------------------------------
// Device-global scratch
// ---------------------------------------------------------------------------
__device__ float g_Q [MROWS * CDIM];
__device__ float g_K [MROWS * CDIM];
__device__ float g_V [MROWS * CDIM];
__device__ float g_AO[MROWS * CDIM];
__device__ float g_tb[225 * NHEADS];
__device__ float g_ls[NHEADS];

__device__ __nv_bfloat16 g_Ahi[MROWS * CDIM];
__device__ __nv_bfloat16 g_Alo[MROWS * CDIM];
__device__ __nv_bfloat16 g_Whi[4 * CDIM * CDIM];
__device__ __nv_bfloat16 g_Wlo[4 * CDIM * CDIM];

// ---------------------------------------------------------------------------
// helpers
// ---------------------------------------------------------------------------
__device__ __forceinline__ uint32_t smem_u32(const void* p)
{
    uint32_t a;
    asm("{ .reg .u64 t; cvta.to.shared.u64 t, %1; cvt.u32.u64 %0, t; }" : "=r"(a) : "l"(p));
    return a;
}

__device__ __forceinline__ void ldsm_x4(uint32_t r[4], uint32_t addr)
{
    asm volatile("ldmatrix.sync.aligned.m8n8.x4.shared.b16 {%0,%1,%2,%3}, [%4];"
                 : "=r"(r[0]), "=r"(r[1]), "=r"(r[2]), "=r"(r[3]) : "r"(addr));
}
__device__ __forceinline__ void ldsm_x4_t(uint32_t r[4], uint32_t addr)
{
    asm volatile("ldmatrix.sync.aligned.m8n8.x4.trans.shared.b16 {%0,%1,%2,%3}, [%4];"
                 : "=r"(r[0]), "=r"(r[1]), "=r"(r[2]), "=r"(r[3]) : "r"(addr));
}
__device__ __forceinline__ void mma_bf16(float c[4], const uint32_t a[4], const uint32_t b[2])
{
    asm volatile(
        "mma.sync.aligned.m16n8k16.row.col.f32.bf16.bf16.f32 "
        "{%0,%1,%2,%3},{%4,%5,%6,%7},{%8,%9},{%0,%1,%2,%3};"
        : "+f"(c[0]), "+f"(c[1]), "+f"(c[2]), "+f"(c[3])
        : "r"(a[0]), "r"(a[1]), "r"(a[2]), "r"(a[3]), "r"(b[0]), "r"(b[1]));
}

// f32x2 packed helpers (attention)
__device__ __forceinline__ ull fma2(ull a, ull b, ull c)
{
    ull d; asm("fma.rn.f32x2 %0, %1, %2, %3;" : "=l"(d) : "l"(a), "l"(b), "l"(c)); return d;
}
__device__ __forceinline__ ull add2(ull a, ull b)
{
    ull d; asm("add.rn.f32x2 %0, %1, %2;" : "=l"(d) : "l"(a), "l"(b)); return d;
}
__device__ __forceinline__ ull pk2(float lo, float hi)
{
    ull r; asm("mov.b64 %0, {%1, %2};" : "=l"(r) : "f"(lo), "f"(hi)); return r;
}
__device__ __forceinline__ float2 upk2(ull v)
{
    float lo, hi; asm("mov.b64 {%0, %1}, %2;" : "=f"(lo), "=f"(hi) : "l"(v)); return make_float2(lo, hi);
}

// ---------------------------------------------------------------------------
// Kernel 0: fp32 -> (bf16 hi, bf16 lo) split, 4 elems/thread
// ---------------------------------------------------------------------------
__global__ void convert_split_kernel(const float* __restrict__ src,
                                     __nv_bfloat16* __restrict__ hi,
                                     __nv_bfloat16* __restrict__ lo, int n4)
{
    int i = blockIdx.x * blockDim.x + threadIdx.x;
    if (i >= n4) return;
    float4 v = reinterpret_cast<const float4*>(src)[i];
    float vv[4] = {v.x, v.y, v.z, v.w};
    __align__(8) __nv_bfloat16 h[4], l[4];
    #pragma unroll
    for (int j = 0; j < 4; j++) {
        h[j] = __float2bfloat16_rn(vv[j]);
        l[j] = __float2bfloat16_rn(vv[j] - __bfloat162float(h[j]));
    }
    reinterpret_cast<uint2*>(hi)[i] = *reinterpret_cast<uint2*>(h);
    reinterpret_cast<uint2*>(lo)[i] = *reinterpret_cast<uint2*>(l);
}

// ---------------------------------------------------------------------------
// Kernel 1: continuous position bias MLP
// ---------------------------------------------------------------------------
__global__ void cpb_kernel(const float* __restrict__ w1, const float* __restrict__ b1,
                           const float* __restrict__ w2, const float* __restrict__ b2,
                           const float* __restrict__ tau)
{
    __shared__ float red[128][12];
    const int m   = blockIdx.x;
    const int tid = threadIdx.x;
    const int ai  = m / 15;
    const int bi  = m % 15;

    float x0 = (float)(bi - 7) * (8.0f / 7.0f);
    float x1 = (float)(ai - 7) * (8.0f / 7.0f);
    float s0 = (x0 > 0.f) ? 1.f : ((x0 < 0.f) ? -1.f : 0.f);
    float s1 = (x1 > 0.f) ? 1.f : ((x1 < 0.f) ? -1.f : 0.f);
    float v0 = s0 * log2f(fabsf(x0) + 1.0f) * (1.0f / 3.0f);
    float v1 = s1 * log2f(fabsf(x1) + 1.0f) * (1.0f / 3.0f);

    float p[NHEADS];
    #pragma unroll
    for (int h = 0; h < NHEADS; h++) p[h] = 0.f;

    for (int c = tid; c < 512; c += 128) {
        float hv = v0 * w1[c] + v1 * w1[512 + c] + b1[c];
        hv = fmaxf(hv, 0.0f);
        #pragma unroll
        for (int h = 0; h < NHEADS; h++) p[h] += hv * w2[c * NHEADS + h];
    }
    #pragma unroll
    for (int h = 0; h < NHEADS; h++) red[tid][h] = p[h];
    __syncthreads();

    if (tid < NHEADS) {
        float s = 0.f;
        for (int t2 = 0; t2 < 128; t2++) s += red[t2][tid];
        g_tb[m * NHEADS + tid] = s + b2[tid];
        if (m == 0) g_ls[tid] = fmaxf(tau[tid] + 2.302585092994046f, 0.01f);
    }
}

// ---------------------------------------------------------------------------
// Kernel 2: C[M,384] = A[M,384] @ W[384,384] (+bias) via split-bf16 3-term.
// Logical K' = 1152: phase 0 (Ahi,Whi), phase 1 (Ahi,Wlo), phase 2 (Alo,Whi).
// Block tile 128x128, K-chunk 32, 8 warps (2x4), warp tile 64x32.
// LDSM fragment loads, register-prefetched staging.
// grid = (3, 576), block = 256
// ---------------------------------------------------------------------------
__global__ __launch_bounds__(256, 2) void gemm_bf16_kernel(
    const __nv_bfloat16* __restrict__ Ahi, const __nv_bfloat16* __restrict__ Alo,
    const __nv_bfloat16* __restrict__ Whi, const __nv_bfloat16* __restrict__ Wlo,
    const float* __restrict__ bias, float* __restrict__ C)
{
    __shared__ __align__(16) __nv_bfloat16 As[128][40];   // rows 80B, LDSM conflict-free
    __shared__ __align__(16) __nv_bfloat16 Bs[32][136];   // rows 272B, LDSM conflict-free

    const int tid  = threadIdx.x;
    const int lane = tid & 31;
    const int warp = tid >> 5;
    const int wm   = warp >> 2;        // 0..1  (64 rows)
    const int wn   = warp & 3;         // 0..3  (32 cols)
    const int rb   = blockIdx.y * 128;
    const int cb   = blockIdx.x * 128;

    // staging indices
    const int ar = tid >> 1;           // 0..127
    const int ac = (tid & 1) * 16;     // 0 or 16
    const int br = tid >> 3;           // 0..31
    const int bc = (tid & 7) * 16;     // 0..112

    // per-lane LDSM address components
    const int g  = lane >> 3;          // matrix group 0..3
    const int lr = lane & 7;
    const int a_row  = wm * 64 + lr + (g & 1) * 8;
    const int a_col  = (g >> 1) * 8;
    const int b_krow = lr + (g & 1) * 8;
    const int b_ncol = wn * 32 + (g >> 1) * 8;

    float acc[4][4][4];
    #pragma unroll
    for (int mi = 0; mi < 4; mi++)
        #pragma unroll
        for (int ni = 0; ni < 4; ni++)
            #pragma unroll
            for (int q = 0; q < 4; q++) acc[mi][ni][q] = 0.f;

    int4 aR0, aR1, bR0, bR1;
    {
        const __nv_bfloat16* ga = &Ahi[(size_t)(rb + ar) * 384 + ac];
        aR0 = *reinterpret_cast<const int4*>(ga);
        aR1 = *reinterpret_cast<const int4*>(ga + 8);
        const __nv_bfloat16* gb = &Whi[(size_t)br * 384 + cb + bc];
        bR0 = *reinterpret_cast<const int4*>(gb);
        bR1 = *reinterpret_cast<const int4*>(gb + 8);
    }

    const uint32_t as_base = smem_u32(&As[0][0]);
    const uint32_t bs_base = smem_u32(&Bs[0][0]);

    for (int cc = 0; cc < 36; cc++) {
        // store staged tile (uint2 stores: rows are 8B-aligned)
        *reinterpret_cast<uint2*>(&As[ar][ac])      = make_uint2((unsigned)aR0.x, (unsigned)aR0.y);
        *reinterpret_cast<uint2*>(&As[ar][ac + 4])  = make_uint2((unsigned)aR0.z, (unsigned)aR0.w);
        *reinterpret_cast<uint2*>(&As[ar][ac + 8])  = make_uint2((unsigned)aR1.x, (unsigned)aR1.y);
        *reinterpret_cast<uint2*>(&As[ar][ac + 12]) = make_uint2((unsigned)aR1.z, (unsigned)aR1.w);
        *reinterpret_cast<int4*>(&Bs[br][bc])       = bR0;
        *reinterpret_cast<int4*>(&Bs[br][bc + 8])   = bR1;
        __syncthreads();

        // prefetch next chunk
        if (cc + 1 < 36) {
            int nc = cc + 1;
            int ph = nc / 12;
            int kl = (nc % 12) * 32;
            const __nv_bfloat16* pA = (ph < 2) ? Ahi : Alo;
            const __nv_bfloat16* pB = (ph == 1) ? Wlo : Whi;
            const __nv_bfloat16* ga = &pA[(size_t)(rb + ar) * 384 + kl + ac];
            aR0 = *reinterpret_cast<const int4*>(ga);
            aR1 = *reinterpret_cast<const int4*>(ga + 8);
            const __nv_bfloat16* gb = &pB[(size_t)(kl + br) * 384 + cb + bc];
            bR0 = *reinterpret_cast<const int4*>(gb);
            bR1 = *reinterpret_cast<const int4*>(gb + 8);
        }

        #pragma unroll
        for (int ks = 0; ks < 2; ks++) {
            uint32_t af[4][4];
            #pragma unroll
            for (int mi = 0; mi < 4; mi++) {
                uint32_t addr = as_base + ((a_row + mi * 16) * 40 + ks * 16 + a_col) * 2;
                ldsm_x4(af[mi], addr);
            }
            uint32_t bf_[2][4];
            #pragma unroll
            for (int nt = 0; nt < 2; nt++) {
                uint32_t addr = bs_base + ((ks * 16 + b_krow) * 136 + b_ncol + nt * 16) * 2;
                ldsm_x4_t(bf_[nt], addr);
            }
            #pragma unroll
            for (int mi = 0; mi < 4; mi++)
                #pragma unroll
                for (int ni = 0; ni < 4; ni++)
                    mma_bf16(acc[mi][ni], af[mi], &bf_[ni >> 1][(ni & 1) * 2]);
        }
        __syncthreads();
    }

    // epilogue
    #pragma unroll
    for (int mi = 0; mi < 4; mi++) {
        #pragma unroll
        for (int ni = 0; ni < 4; ni++) {
            int r = rb + wm * 64 + mi * 16 + (lane >> 2);
            int c = cb + wn * 32 + ni * 8 + (lane & 3) * 2;
            float b0 = bias ? bias[c]     : 0.f;
            float b1 = bias ? bias[c + 1] : 0.f;
            float2 v0 = make_float2(acc[mi][ni][0] + b0, acc[mi][ni][1] + b1);
            float2 v1 = make_float2(acc[mi][ni][2] + b0, acc[mi][ni][3] + b1);
            *reinterpret_cast<float2*>(&C[(size_t)r * 384 + c])       = v0;
            *reinterpret_cast<float2*>(&C[(size_t)(r + 8) * 384 + c]) = v1;
        }
    }
}

// ---------------------------------------------------------------------------
// Kernel 3: per-(window, head) attention, f32x2-packed math
// grid = (1152, 12), block = 128
// ---------------------------------------------------------------------------
__global__ __launch_bounds__(128) void attn_kernel(const float* __restrict__ mask)
{
    __shared__ float qs [NTOK * DH];
    __shared__ float kss[NTOK * DH];
    __shared__ float vss[NTOK * DH];
    __shared__ float at [NTOK * 65];
    __shared__ float qn [NTOK];
    __shared__ float kn [NTOK];
    __shared__ float tbs[225];

    const int b   = blockIdx.x;
    const int h   = blockIdx.y;
    const int tid = threadIdx.x;
    const size_t base = (size_t)b * NTOK * CDIM + h * DH;

    for (int idx = tid; idx < 512; idx += 128) {
        int n = idx >> 3;
        int d = (idx & 7) << 2;
        size_t ga = base + (size_t)n * CDIM + d;
        *reinterpret_cast<float4*>(&qs [n * DH + d]) = *reinterpret_cast<const float4*>(&g_Q[ga]);
        *reinterpret_cast<float4*>(&kss[n * DH + d]) = *reinterpret_cast<const float4*>(&g_K[ga]);
        *reinterpret_cast<float4*>(&vss[n * DH + d]) = *reinterpret_cast<const float4*>(&g_V[ga]);
    }
    for (int i = tid; i < 225; i += 128) tbs[i] = g_tb[i * NHEADS + h];
    const float ls = g_ls[h];
    __syncthreads();

    {
        const float* src = (tid < 64) ? qs : kss;
        int i = (tid < 64) ? tid : (tid - 64);
        const ulonglong2* p = reinterpret_cast<const ulonglong2*>(&src[i * DH]);
        ull a0 = 0ull, a1 = 0ull;
        #pragma unroll
        for (int u = 0; u < 8; u++) {
            ulonglong2 v = p[u];
            a0 = fma2(v.x, v.x, a0);
            a1 = fma2(v.y, v.y, a1);
        }
        float2 s2 = upk2(add2(a0, a1));
        float nrm = sqrtf(s2.x + s2.y);
        if (tid < 64) qn[i] = nrm; else kn[i] = nrm;
    }
    __syncthreads();

    {
        const int i  = tid >> 1;
        const int cg = tid & 1;
        ull q2[16];
        {
            const ulonglong2* qp = reinterpret_cast<const ulonglong2*>(&qs[i * DH]);
            #pragma unroll
            for (int u = 0; u < 8; u++) { ulonglong2 v = qp[u]; q2[2 * u] = v.x; q2[2 * u + 1] = v.y; }
        }
        const float qni = qn[i];
        const int ri = i >> 3, ci = i & 7;
        #pragma unroll 4
        for (int jj = 0; jj < 32; jj++) {
            int j = cg * 32 + jj;
            const ulonglong2* kp = reinterpret_cast<const ulonglong2*>(&kss[j * DH]);
            ull a0 = 0ull, a1 = 0ull, a2 = 0ull, a3 = 0ull;
            #pragma unroll
            for (int u = 0; u < 4; u++) {
                ulonglong2 v0 = kp[2 * u];
                ulonglong2 v1 = kp[2 * u + 1];
                a0 = fma2(q2[4 * u    ], v0.x, a0);
                a1 = fma2(q2[4 * u + 1], v0.y, a1);
                a2 = fma2(q2[4 * u + 2], v1.x, a2);
                a3 = fma2(q2[4 * u + 3], v1.y, a3);
            }
            float2 s2 = upk2(add2(add2(a0, a1), add2(a2, a3)));
            float dot = s2.x + s2.y;
            float den = fmaxf(qni * kn[j], 1e-6f);
            int idx = ((ri - (j >> 3)) + 7) * 15 + (ci - (j & 7)) + 7;
            float bias = 16.0f / (1.0f + __expf(-tbs[idx]));
            at[i * 65 + j] = dot / den * ls + bias;
        }
    }
    __syncthreads();

    {
        const float* mrow = mask + (size_t)b * 4096;
        for (int idx = tid; idx < 1024; idx += 128) {
            float4 mv = reinterpret_cast<const float4*>(mrow)[idx];
            int f = idx << 2;
            int i = f >> 6, j = f & 63;
            at[i * 65 + j]     += mv.x;
            at[i * 65 + j + 1] += mv.y;
            at[i * 65 + j + 2] += mv.z;
            at[i * 65 + j + 3] += mv.w;
        }
    }
    __syncthreads();

    if (tid < 64) {
        float* row = &at[tid * 65];
        float m = row[0];
        #pragma unroll 8
        for (int j = 1; j < 64; j++) m = fmaxf(m, row[j]);
        float s = 0.f;
        #pragma unroll 8
        for (int j = 0; j < 64; j++) { float e = __expf(row[j] - m); row[j] = e; s += e; }
        float inv = 1.0f / s;
        #pragma unroll 8
        for (int j = 0; j < 64; j++) row[j] *= inv;
    }
    __syncthreads();

    {
        const int i  = tid >> 1;
        const int cg = tid & 1;
        ull acc2[8];
        #pragma unroll
        for (int u = 0; u < 8; u++) acc2[u] = 0ull;
        #pragma unroll 4
        for (int j = 0; j < 64; j++) {
            float p = at[i * 65 + j];
            ull p2 = pk2(p, p);
            const ulonglong2* vp = reinterpret_cast<const ulonglong2*>(&vss[j * DH + cg * 16]);
            #pragma unroll
            for (int u = 0; u < 4; u++) {
                ulonglong2 v = vp[u];
                acc2[2 * u]     = fma2(p2, v.x, acc2[2 * u]);
                acc2[2 * u + 1] = fma2(p2, v.y, acc2[2 * u + 1]);
            }
        }
        size_t ob = (size_t)(b * NTOK + i) * CDIM + h * DH + cg * 16;
        #pragma unroll
        for (int u = 0; u < 4; u++) {
            ulonglong2 st;
            st.x = acc2[2 * u];
            st.y = acc2[2 * u + 1];
            *reinterpret_cast<ulonglong2*>(&g_AO[ob + 4 * u]) = st;
        }
    }
}

// ---------------------------------------------------------------------------
// Launch
// ---------------------------------------------------------------------------
extern "C" void kernel_launch(void* const* d_in, const int* in_sizes, int n_in,
                              void* d_out, int out_size)
{
    (void)in_sizes; (void)n_in; (void)out_size;
    const float* x     = (const float*)d_in[0];
    const float* mask  = (const float*)d_in[1];
    const float* wq    = (const float*)d_in[2];
    const float* bq    = (const float*)d_in[3];
    const float* wk    = (const float*)d_in[4];
    const float* wv    = (const float*)d_in[5];
    const float* bv    = (const float*)d_in[6];
    const float* cw1   = (const float*)d_in[7];
    const float* cb1   = (const float*)d_in[8];
    const float* cw2   = (const float*)d_in[9];
    const float* cb2   = (const float*)d_in[10];
    const float* tau   = (const float*)d_in[11];
    const float* wproj = (const float*)d_in[12];
    const float* bproj = (const float*)d_in[13];
    float* out = (float*)d_out;

    float *pQ, *pK, *pV, *pAO;
    __nv_bfloat16 *pAhi, *pAlo, *pWhi, *pWlo;
    cudaGetSymbolAddress((void**)&pQ,   g_Q);
    cudaGetSymbolAddress((void**)&pK,   g_K);
    cudaGetSymbolAddress((void**)&pV,   g_V);
    cudaGetSymbolAddress((void**)&pAO,  g_AO);
    cudaGetSymbolAddress((void**)&pAhi, g_Ahi);
    cudaGetSymbolAddress((void**)&pAlo, g_Alo);
    cudaGetSymbolAddress((void**)&pWhi, g_Whi);
    cudaGetSymbolAddress((void**)&pWlo, g_Wlo);

    const int WN = CDIM * CDIM;          // 147456
    const int wn4 = WN / 4;              // 36864
    const int xn4 = MROWS * CDIM / 4;    // 7077888

    // splits
    convert_split_kernel<<<(xn4 + 255) / 256, 256>>>(x, pAhi, pAlo, xn4);
    convert_split_kernel<<<(wn4 + 255) / 256, 256>>>(wq,    pWhi + 0 * WN, pWlo + 0 * WN, wn4);
    convert_split_kernel<<<(wn4 + 255) / 256, 256>>>(wk,    pWhi + 1 * WN, pWlo + 1 * WN, wn4);
    convert_split_kernel<<<(wn4 + 255) / 256, 256>>>(wv,    pWhi + 2 * WN, pWlo + 2 * WN, wn4);
    convert_split_kernel<<<(wn4 + 255) / 256, 256>>>(wproj, pWhi + 3 * WN, pWlo + 3 * WN, wn4);

    cpb_kernel<<<225, 128>>>(cw1, cb1, cw2, cb2, tau);

    dim3 gg(CDIM / 128, MROWS / 128);    // (3, 576)
    gemm_bf16_kernel<<<gg, 256>>>(pAhi, pAlo, pWhi + 0 * WN, pWlo + 0 * WN, bq,      pQ);
    gemm_bf16_kernel<<<gg, 256>>>(pAhi, pAlo, pWhi + 1 * WN, pWlo + 1 * WN, nullptr, pK);
    gemm_bf16_kernel<<<gg, 256>>>(pAhi, pAlo, pWhi + 2 * WN, pWlo + 2 * WN, bv,      pV);

    attn_kernel<<<dim3(NWIN, NHEADS), 128>>>(mask);

    convert_split_kernel<<<(xn4 + 255) / 256, 256>>>(pAO, pAhi, pAlo, xn4);
    gemm_bf16_kernel<<<gg, 256>>>(pAhi, pAlo, pWhi + 3 * WN, pWlo + 3 * WN, bproj, out);
}